// round 2
// baseline (speedup 1.0000x reference)
#include <cuda_runtime.h>
#include <math.h>

// AttnPooling: B=8, N=16, D=128, H=W=64 -> K=4096, BN=128 (b,n) pairs.
//
// Algebra: softmax logits l[k] = q . (Wk x_k + bk) = (Wk^T q) . x_k + const,
// const cancels in softmax. So per (b,n):
//   pass A: mean = (sum_k m_k x_k)/count; q = Wq mean + bq; q2 = (Wk^T q)/sqrt(D)
//   pass B: online softmax over k with logit q2 . x_k, pooled = sum attn_k x_k.
// One block per (b,n); both passes stream the block's private 2MB slice.

#define BN 128
#define DD 128
#define KK 4096
#define TT 128            // k-tile
#define NT (KK / TT)      // 32 tiles
#define NTHREADS 512
#define TS 132            // padded tile row stride (floats); 132%32=4, lane-along-k access is stride-1 so conflict-free
#define BUFSZ (DD * TS)
// smem layout (floats)
#define OFF_MASK  0
#define OFF_TILE  4096
#define OFF_MEAN  (OFF_TILE + 2*BUFSZ)       // 37888
#define OFF_Q     (OFF_MEAN + 128)
#define OFF_Q2    (OFF_Q + 128)
#define OFF_LOGIT (OFF_Q2 + 128)
#define OFF_W     (OFF_LOGIT + 128)
#define OFF_PART  (OFF_W + 128)
#define OFF_RED   (OFF_PART + 512)
#define OFF_P     (OFF_RED + 32)
#define OFF_SCAL  (OFF_P + 128)
#define SMEM_FLOATS (OFF_SCAL + 8)

__device__ __forceinline__ float warp_sum(float v) {
#pragma unroll
    for (int o = 16; o > 0; o >>= 1) v += __shfl_xor_sync(0xffffffffu, v, o);
    return v;
}
__device__ __forceinline__ float warp_max(float v) {
#pragma unroll
    for (int o = 16; o > 0; o >>= 1) v = fmaxf(v, __shfl_xor_sync(0xffffffffu, v, o));
    return v;
}

__global__ void __launch_bounds__(NTHREADS, 1)
attn_pool_kernel(const float* __restrict__ x, const int* __restrict__ mask,
                 const float* __restrict__ Wq, const float* __restrict__ bq,
                 const float* __restrict__ Wk, const float* __restrict__ bk,
                 float* __restrict__ out)
{
    extern __shared__ float sm[];
    float* mask_s  = sm + OFF_MASK;   // 4096 mask values as float
    float* tile    = sm + OFF_TILE;   // 2 x [128][TS] double-buffered k-tile
    float* mean_s  = sm + OFF_MEAN;
    float* q_s     = sm + OFF_Q;
    float* q2_s    = sm + OFF_Q2;
    float* logit_s = sm + OFF_LOGIT;
    float* w_s     = sm + OFF_W;
    float* part_s  = sm + OFF_PART;   // 512 logit partials / final s partials
    float* red_s   = sm + OFF_RED;
    float* p_s     = sm + OFF_P;
    float* scal    = sm + OFF_SCAL;   // [0]=count [1]=running max [3]=alpha

    const int tid  = threadIdx.x;
    const int lane = tid & 31;
    const int wid  = tid >> 5;
    const int bn   = blockIdx.x;
    const float NEG_INF = __int_as_float(0xff800000);

    const float* xb = x + (size_t)bn * (size_t)(DD * KK);
    const int*   mb = mask + (size_t)bn * KK;

    // ---------------- Pass A: mask load + count ----------------
    float c = 0.f;
    for (int i = tid; i < KK; i += NTHREADS) {
        float v = (float)mb[i];
        mask_s[i] = v;
        c += v;
    }
    c = warp_sum(c);
    if (lane == 0) red_s[wid] = c;
    __syncthreads();
    if (wid == 0) {
        float v = (lane < 16) ? red_s[lane] : 0.f;
        v = warp_sum(v);
        if (lane == 0) scal[0] = v;
    }
    __syncthreads();

    // masked mean: warp per d-row (rows wid, wid+16, ...)
    const float inv_cnt = 1.0f / scal[0];
    const float4* m4 = (const float4*)mask_s;
#pragma unroll
    for (int r = 0; r < 8; r++) {
        int d = wid + 16 * r;
        const float4* row = (const float4*)(xb + (size_t)d * KK);
        float s = 0.f;
        for (int i = lane; i < KK / 4; i += 32) {
            float4 v = row[i];
            float4 mm = m4[i];
            s = fmaf(v.x, mm.x, s);
            s = fmaf(v.y, mm.y, s);
            s = fmaf(v.z, mm.z, s);
            s = fmaf(v.w, mm.w, s);
        }
        s = warp_sum(s);
        if (lane == 0) mean_s[d] = s * inv_cnt;
    }
    __syncthreads();

    // q[d] = bq[d] + sum_j Wq[d][j] * mean[j]  (warp per row, coalesced along j)
#pragma unroll
    for (int r = 0; r < 8; r++) {
        int d = wid * 8 + r;
        float s = 0.f;
#pragma unroll
        for (int i = 0; i < 4; i++) {
            int j = lane + 32 * i;
            s = fmaf(Wq[d * DD + j], mean_s[j], s);
        }
        s = warp_sum(s);
        if (lane == 0) q_s[d] = s + bq[d];
    }
    __syncthreads();

    // q2[t] = (sum_j Wk[j][t] * q[j]) / sqrt(D)  (thread per column, coalesced along t)
    if (tid < DD) {
        float s = 0.f;
#pragma unroll 8
        for (int j = 0; j < DD; j++)
            s = fmaf(Wk[j * DD + tid], q_s[j], s);
        q2_s[tid] = s * 0.08838834764831845f;  // 1/sqrt(128)
    }
    if (tid == 0) { scal[1] = NEG_INF; scal[3] = 0.f; }
    __syncthreads();

    // ---------------- Pass B: online-softmax pooling ----------------
    // Thread-distributed accumulators: p_dist[r] covers d = wid+16r, k in {lane+32*i}.
    float p_dist[8];
#pragma unroll
    for (int r = 0; r < 8; r++) p_dist[r] = 0.f;
    float s_part = 0.f;  // distributed softmax denominator partial (tid<128 meaningful)

    float4 pre[8];
    // prime tile 0 into buffer 0
#pragma unroll
    for (int r = 0; r < 8; r++) {
        int d = wid + 16 * r;
        pre[r] = *(const float4*)(xb + (size_t)d * KK + lane * 4);
    }
#pragma unroll
    for (int r = 0; r < 8; r++) {
        int d = wid + 16 * r;
        *(float4*)(tile + d * TS + lane * 4) = pre[r];
    }
    __syncthreads();

    for (int t = 0; t < NT; t++) {
        float* X  = tile + (t & 1) * BUFSZ;
        float* Xn = tile + ((t + 1) & 1) * BUFSZ;

        // prefetch next tile into registers (latency hidden behind compute)
        if (t + 1 < NT) {
#pragma unroll
            for (int r = 0; r < 8; r++) {
                int d = wid + 16 * r;
                pre[r] = *(const float4*)(xb + (size_t)d * KK + (t + 1) * TT + lane * 4);
            }
        }

        // logit partials: thread (k = tid&127, g = tid>>7) sums 32 d's
        {
            int k = tid & 127;
            int g = tid >> 7;
            const float* col = X + k;
            float acc = 0.f;
#pragma unroll
            for (int j = 0; j < 32; j++) {
                int d = g * 32 + j;
                acc = fmaf(q2_s[d], col[d * TS], acc);
            }
            part_s[g * 128 + k] = acc;
        }
        __syncthreads();

        // combine partials, apply mask, tile max
        float l = NEG_INF;
        if (tid < 128) {
            l = part_s[tid] + part_s[128 + tid] + part_s[256 + tid] + part_s[384 + tid];
            if (mask_s[t * TT + tid] == 0.f) l = NEG_INF;
            logit_s[tid] = l;
        }
        float mx = warp_max(l);
        if (tid < 128 && lane == 0) red_s[wid] = mx;
        __syncthreads();

        if (tid == 0) {
            float tm = fmaxf(fmaxf(red_s[0], red_s[1]), fmaxf(red_s[2], red_s[3]));
            float M  = scal[1];
            float nM = fmaxf(M, tm);
            float alpha = (nM == NEG_INF) ? 0.f : __expf(M - nM);
            scal[1] = nM;
            scal[3] = alpha;
        }
        __syncthreads();

        const float nM    = scal[1];
        const float alpha = scal[3];

        // weights + distributed denominator
        if (tid < 128) {
            float w = (mask_s[t * TT + tid] != 0.f) ? __expf(logit_s[tid] - nM) : 0.f;
            w_s[tid] = w;
            s_part = s_part * alpha + w;
        }
        __syncthreads();

        // weighted accumulation, no per-tile reduction (distributed partials)
#pragma unroll
        for (int r = 0; r < 8; r++) {
            int d = wid + 16 * r;
            const float* row = X + d * TS;
            float rs = 0.f;
#pragma unroll
            for (int i = 0; i < 4; i++) {
                int k = lane + 32 * i;
                rs = fmaf(w_s[k], row[k], rs);
            }
            p_dist[r] = p_dist[r] * alpha + rs;
        }

        // commit prefetched tile to the other buffer
        if (t + 1 < NT) {
#pragma unroll
            for (int r = 0; r < 8; r++) {
                int d = wid + 16 * r;
                *(float4*)(Xn + d * TS + lane * 4) = pre[r];
            }
        }
        __syncthreads();
    }

    // ---------------- Epilogue ----------------
#pragma unroll
    for (int r = 0; r < 8; r++) {
        float rs = warp_sum(p_dist[r]);
        if (lane == 0) p_s[wid + 16 * r] = rs;
    }
    if (tid < 128) part_s[tid] = s_part;
    __syncthreads();
    if (wid == 0) {
        float v = part_s[lane] + part_s[lane + 32] + part_s[lane + 64] + part_s[lane + 96];
        v = warp_sum(v);
        if (lane == 0) scal[2] = v;
    }
    __syncthreads();
    if (tid < DD) {
        out[bn * DD + tid] = p_s[tid] / scal[2];
    }
}

extern "C" void kernel_launch(void* const* d_in, const int* in_sizes, int n_in,
                              void* d_out, int out_size) {
    const float* x    = (const float*)d_in[0];
    const int*   mask = (const int*)d_in[1];
    const float* Wq   = (const float*)d_in[2];
    const float* bq   = (const float*)d_in[3];
    const float* Wk   = (const float*)d_in[4];
    const float* bk   = (const float*)d_in[5];
    float* out = (float*)d_out;
    (void)bk; (void)in_sizes; (void)n_in; (void)out_size;  // bk const cancels in softmax

    size_t smem = (size_t)SMEM_FLOATS * sizeof(float);
    cudaFuncSetAttribute(attn_pool_kernel,
                         cudaFuncAttributeMaxDynamicSharedMemorySize, (int)smem);
    attn_pool_kernel<<<BN, NTHREADS, smem>>>(x, mask, Wq, bq, Wk, bk, out);
}